// round 14
// baseline (speedup 1.0000x reference)
#include <cuda_runtime.h>
#include <cstdint>

#define B_    8
#define N1_   16384
#define N2_   2048
#define C1_   128
#define C2_   256
#define INCH_ 384
#define H1_   256
#define H2_   128
#define M_    (B_ * N1_)            // 131072 rows
#define MT_   (M_ / 128)            // 1024 M-tiles (partial-stat blocks)
#define BN_EPS 1e-5f

#define STAGES 3
#define STAGE_FLOATS (128 * 20)                      // one operand stage
#define GEMM_SMEM_BYTES (STAGES * STAGE_FLOATS * 2 * 4)   // 61440 B

// ---------------- scratch (device globals; no cudaMalloc allowed) ----------------
__device__ float g_x  [(size_t)M_ * INCH_];   // concat(points1, interp), tf32-rounded
__device__ float g_h1 [(size_t)M_ * H1_];     // GEMM1 out (pre-BN, fp32)  [M,256]
__device__ float g_h2 [(size_t)M_ * H2_];     // GEMM2 out (pre-BN, fp32)  [M,128]
__device__ float g_wc1[(size_t)H1_ * INCH_];  // W1 pre-converted to tf32 bits
__device__ float g_wc2[(size_t)H2_ * H1_];    // W2 pre-converted to tf32 bits
__device__ float g_psum[(size_t)MT_ * H1_];
__device__ float g_psq [(size_t)MT_ * H1_];
__device__ float g_scale1[H1_], g_shift1[H1_];
__device__ float g_scale2[H2_], g_shift2[H2_];

__device__ __forceinline__ uint32_t f2tf32(float x) {
    uint32_t u;
    asm("cvt.rna.tf32.f32 %0, %1;" : "=r"(u) : "f"(x));
    return u;
}
__device__ __forceinline__ float f2tf32f(float x) { return __uint_as_float(f2tf32(x)); }

// ---------------- one-time weight tf32 pre-convert ----------------
__global__ void cvt_weights_kernel(const float* __restrict__ W, float* __restrict__ Wc, int n) {
    int i = blockIdx.x * 256 + threadIdx.x;
    if (i < n) Wc[i] = f2tf32f(W[i]);
}

// ---------------- 3-NN + interpolation + concat (tf32-rounded output) ----------------
#define QPT 4
#define KNN_T 128
#define QPB (QPT * KNN_T)   // 512 queries per block

__global__ __launch_bounds__(KNN_T)
void knn_interp_kernel(const float* __restrict__ xyz1, const float* __restrict__ xyz2,
                       const float* __restrict__ points1, const float* __restrict__ points2,
                       float* __restrict__ x_out) {
    __shared__ float sx[N2_], sy[N2_], sz[N2_];
    __shared__ int   s_idx[QPB][3];
    __shared__ float s_w  [QPB][3];

    const int b   = blockIdx.y;
    const int q0  = blockIdx.x * QPB;
    const int tid = threadIdx.x;

    const float* x2 = xyz2 + (size_t)b * N2_ * 3;
    for (int j = tid; j < N2_; j += KNN_T) {
        float3 v = ((const float3*)x2)[j];
        sx[j] = v.x; sy[j] = v.y; sz[j] = v.z;
    }
    __syncthreads();

    float px[QPT], py[QPT], pz[QPT];
    float d0[QPT], d1[QPT], d2[QPT];
    int   i0[QPT], i1[QPT], i2[QPT];
#pragma unroll
    for (int i = 0; i < QPT; i++) {
        const int q = q0 + i * KNN_T + tid;
        float3 p = ((const float3*)(xyz1 + (size_t)b * N1_ * 3))[q];
        px[i] = p.x; py[i] = p.y; pz[i] = p.z;
        d0[i] = 1e30f; d1[i] = 1e30f; d2[i] = 1e30f;
        i0[i] = 0; i1[i] = 0; i2[i] = 0;
    }

#pragma unroll 4
    for (int j = 0; j < N2_; j++) {
        const float cx = sx[j], cy = sy[j], cz = sz[j];
#pragma unroll
        for (int i = 0; i < QPT; i++) {
            float dx = px[i] - cx;
            float dy = py[i] - cy;
            float dz = pz[i] - cz;
            float d  = fmaf(dx, dx, fmaf(dy, dy, dz * dz));
            if (d < d2[i]) {
                if (d < d0[i])      { d2[i]=d1[i]; i2[i]=i1[i]; d1[i]=d0[i]; i1[i]=i0[i]; d0[i]=d; i0[i]=j; }
                else if (d < d1[i]) { d2[i]=d1[i]; i2[i]=i1[i]; d1[i]=d;  i1[i]=j; }
                else                { d2[i]=d;  i2[i]=j; }
            }
        }
    }

#pragma unroll
    for (int i = 0; i < QPT; i++) {
        float a0 = 1.0f / fmaxf(d0[i], 1e-10f);
        float a1 = 1.0f / fmaxf(d1[i], 1e-10f);
        float a2 = 1.0f / fmaxf(d2[i], 1e-10f);
        float inv = 1.0f / fmaxf(a0 + a1 + a2, 1e-8f);
        const int lq = i * KNN_T + tid;
        s_idx[lq][0] = i0[i]; s_idx[lq][1] = i1[i]; s_idx[lq][2] = i2[i];
        s_w[lq][0] = a0 * inv; s_w[lq][1] = a1 * inv; s_w[lq][2] = a2 * inv;
    }
    __syncthreads();

    const int warp = tid >> 5, lane = tid & 31;
    const float* p2  = points2 + (size_t)b * N2_ * C2_;
    const float* p1b = points1 + ((size_t)b * N1_ + q0) * C1_;
    float* xb = x_out + ((size_t)b * N1_ + q0) * INCH_;

    for (int lq = warp; lq < QPB; lq += 4) {
        const int   j0 = s_idx[lq][0], j1 = s_idx[lq][1], j2 = s_idx[lq][2];
        const float a0 = s_w[lq][0],   a1 = s_w[lq][1],   a2 = s_w[lq][2];
        const float* r0 = p2 + (size_t)j0 * C2_;
        const float* r1 = p2 + (size_t)j1 * C2_;
        const float* r2 = p2 + (size_t)j2 * C2_;
        float* xrow = xb + (size_t)lq * INCH_;
#pragma unroll
        for (int c = lane; c < C2_; c += 32)
            xrow[C1_ + c] = f2tf32f(fmaf(a0, r0[c], fmaf(a1, r1[c], a2 * r2[c])));
        const float* pr = p1b + (size_t)lq * C1_;
#pragma unroll
        for (int c = lane; c < C1_; c += 32)
            xrow[c] = f2tf32f(pr[c]);
    }
}

// ---------------- tf32 TC GEMM: cp.async 3-stage pipeline + fused BN stats ----------
// C[M,N] = op(A)[M,K] @ W[N,K]^T. Block 128x128, 8 warps (4M x 2N), BK=16.
// 3 smem stages (dynamic, 61.4 KB): loads of tiles kt+1 and kt+2 stay in
// flight while computing tile kt -> ~2 tile-computes of latency cover.
// A/B pre-tf32-rounded unless BN (A raw fp32, BN+ReLU+cvt on fragments).
// Epilogue: deterministic per-column sum/sum^2 partials -> psum/psq.

#define LDSM4(R, ADDR)                                                          \
    asm volatile("ldmatrix.sync.aligned.m8n8.x4.shared.b16 {%0,%1,%2,%3}, [%4];"\
                 : "=r"(R[0]), "=r"(R[1]), "=r"(R[2]), "=r"(R[3]) : "r"(ADDR))

#define MMA_TF32(D, A, B0, B1)                                                  \
    asm volatile("mma.sync.aligned.m16n8k8.row.col.f32.tf32.tf32.f32 "          \
                 "{%0,%1,%2,%3},{%4,%5,%6,%7},{%8,%9},{%0,%1,%2,%3};"           \
                 : "+f"(D[0]), "+f"(D[1]), "+f"(D[2]), "+f"(D[3])               \
                 : "r"(A[0]), "r"(A[1]), "r"(A[2]), "r"(A[3]), "r"(B0), "r"(B1))

#define CP16(DST, SRC)                                                          \
    asm volatile("cp.async.cg.shared.global [%0], [%1], 16;" :: "r"(DST), "l"(SRC))
#define CP_COMMIT() asm volatile("cp.async.commit_group;")
#define CP_WAIT0()  asm volatile("cp.async.wait_group 0;")
#define CP_WAIT1()  asm volatile("cp.async.wait_group 1;")

template <int K, int N, bool BN>
__global__ __launch_bounds__(256, 2)
void gemm_tc(const float* __restrict__ A, const float* __restrict__ W,
             const float* __restrict__ scale, const float* __restrict__ shift,
             float* __restrict__ C,
             float* __restrict__ psum, float* __restrict__ psq) {
    extern __shared__ float smem[];
    // layout: As[STAGES][128][20] then Bs[STAGES][128][20]
    float* AsBase = smem;
    float* BsBase = smem + STAGES * STAGE_FLOATS;
    // reduction reuse (after mainloop): s[128][33], q[128][33]
    float (*rs)[33] = (float(*)[33])smem;
    float (*rq)[33] = (float(*)[33])(smem + 128 * 33);

    const int tid  = threadIdx.x;
    const int lane = tid & 31;
    const int warp = tid >> 5;
    const int wm   = warp & 3;
    const int wn   = warp >> 2;
    const int m0   = blockIdx.x * 128;
    const int n0   = blockIdx.y * 128;
    const int l3   = lane & 3;

    const int sr = tid & 127;
    const int sc = (tid >> 7) * 8;
    const float* Ap = A + (size_t)(m0 + sr) * K + sc;
    const float* Wp = W + (size_t)(n0 + sr) * K + sc;
    uint32_t sA[STAGES], sB[STAGES];
#pragma unroll
    for (int st = 0; st < STAGES; st++) {
        sA[st] = (uint32_t)__cvta_generic_to_shared(AsBase + st * STAGE_FLOATS + sr * 20 + sc);
        sB[st] = (uint32_t)__cvta_generic_to_shared(BsBase + st * STAGE_FLOATS + sr * 20 + sc);
    }

    const int r8  = lane & 7;
    const int sel = lane >> 3;
    uint32_t a_addr[STAGES][2][2], b_addr[STAGES][4][2];   // [stage][...][chunk]
#pragma unroll
    for (int st = 0; st < STAGES; st++) {
        uint32_t ab = (uint32_t)__cvta_generic_to_shared(AsBase + st * STAGE_FLOATS);
        uint32_t bb = (uint32_t)__cvta_generic_to_shared(BsBase + st * STAGE_FLOATS);
#pragma unroll
        for (int mt = 0; mt < 2; mt++)
#pragma unroll
            for (int c = 0; c < 2; c++)
                a_addr[st][mt][c] = ab +
                    (((wm * 32 + mt * 16) + r8 + (sel & 1) * 8) * 20 + c * 8 + (sel & 2) * 2) * 4;
#pragma unroll
        for (int p = 0; p < 4; p++)
#pragma unroll
            for (int c = 0; c < 2; c++)
                b_addr[st][p][c] = bb +
                    (((wn * 64 + p * 16) + r8 + (sel >> 1) * 8) * 20 + c * 8 + (sel & 1) * 4) * 4;
    }

    float acc[2][8][4];
#pragma unroll
    for (int mt = 0; mt < 2; mt++)
#pragma unroll
        for (int nt = 0; nt < 8; nt++)
#pragma unroll
            for (int i = 0; i < 4; i++) acc[mt][nt][i] = 0.0f;

    const int KT = K / 16;
    // prologue: issue tiles 0 and 1 (2 groups in flight)
#pragma unroll
    for (int pt = 0; pt < 2; pt++) {
        const int k0 = pt * 16;
        CP16(sA[pt],      Ap + k0);
        CP16(sA[pt] + 16, Ap + k0 + 4);
        CP16(sB[pt],      Wp + k0);
        CP16(sB[pt] + 16, Wp + k0 + 4);
        CP_COMMIT();
    }

#pragma unroll 1
    for (int kt = 0; kt < KT; kt++) {
        const int buf = kt % STAGES;
        // tile kt is the oldest outstanding group; allow 1 newer in flight
        if (kt + 1 < KT) CP_WAIT1(); else CP_WAIT0();
        // Single barrier: proves every warp finished computing tile kt-1,
        // so stage (kt+2)%STAGES (held tile kt-1) is free to overwrite.
        __syncthreads();
        if (kt + 2 < KT) {
            const int k0n = (kt + 2) * 16;
            const int nb  = (kt + 2) % STAGES;
            CP16(sA[nb],      Ap + k0n);
            CP16(sA[nb] + 16, Ap + k0n + 4);
            CP16(sB[nb],      Wp + k0n);
            CP16(sB[nb] + 16, Wp + k0n + 4);
            CP_COMMIT();
        }

        float bns[2][2], bnh[2][2];      // [chunk][khalf]
        if (BN) {
            const int kb = kt * 16 + l3;
#pragma unroll
            for (int c = 0; c < 2; c++)
#pragma unroll
                for (int h = 0; h < 2; h++) {
                    bns[c][h] = scale[kb + c * 8 + h * 4];
                    bnh[c][h] = shift[kb + c * 8 + h * 4];
                }
        }

#pragma unroll
        for (int c = 0; c < 2; c++) {
            uint32_t af[2][4];
            LDSM4(af[0], a_addr[buf][0][c]);
            LDSM4(af[1], a_addr[buf][1][c]);
            uint32_t bf[4][4];
#pragma unroll
            for (int p = 0; p < 4; p++) LDSM4(bf[p], b_addr[buf][p][c]);

            if (BN) {
#pragma unroll
                for (int mt = 0; mt < 2; mt++)
#pragma unroll
                    for (int r = 0; r < 4; r++) {
                        float v = __uint_as_float(af[mt][r]);
                        v = fmaxf(fmaf(v, bns[c][(r >> 1) & 1], bnh[c][(r >> 1) & 1]), 0.0f);
                        af[mt][r] = f2tf32(v);
                    }
            }

#pragma unroll
            for (int mt = 0; mt < 2; mt++)
#pragma unroll
                for (int nt = 0; nt < 8; nt++) {
                    const int p = nt >> 1, wh = nt & 1;
                    MMA_TF32(acc[mt][nt], af[mt], bf[p][wh * 2], bf[p][wh * 2 + 1]);
                }
        }
    }

    // ---- write C tile ----
    const int rr = lane >> 2;
    const int cc = l3 * 2;
#pragma unroll
    for (int mt = 0; mt < 2; mt++)
#pragma unroll
        for (int nt = 0; nt < 8; nt++) {
            const int row = m0 + wm * 32 + mt * 16 + rr;
            const int col = n0 + wn * 64 + nt * 8 + cc;
            float2 v0 = { acc[mt][nt][0], acc[mt][nt][1] };
            float2 v1 = { acc[mt][nt][2], acc[mt][nt][3] };
            *(float2*)&C[(size_t)row * N + col]       = v0;
            *(float2*)&C[(size_t)(row + 8) * N + col] = v1;
        }

    // ---- fused per-block BN stats (deterministic fixed-order reduction) ----
    __syncthreads();   // all LDSM done; smem reusable
    const int contrib = wm * 8 + rr;
#pragma unroll
    for (int nt = 0; nt < 8; nt++)
#pragma unroll
        for (int d = 0; d < 2; d++) {
            const int colL = wn * 64 + nt * 8 + cc + d;
            float s = 0.0f, q = 0.0f;
#pragma unroll
            for (int mt = 0; mt < 2; mt++) {
                float v0 = acc[mt][nt][d];
                float v1 = acc[mt][nt][d + 2];
                s += v0 + v1;
                q += v0 * v0 + v1 * v1;
            }
            rs[colL][contrib] = s;
            rq[colL][contrib] = q;
        }
    __syncthreads();
    if (tid < 128) {
        float s = 0.0f, q = 0.0f;
#pragma unroll 8
        for (int i = 0; i < 32; i++) { s += rs[tid][i]; q += rq[tid][i]; }
        psum[(size_t)blockIdx.x * N + n0 + tid] = s;
        psq [(size_t)blockIdx.x * N + n0 + tid] = q;
    }
}

// ---------------- parallel BN reduce: one block per channel ----------------
template <int C, int PB>
__global__ void reduce_kernel(const float* __restrict__ psum, const float* __restrict__ psq,
                              const float* __restrict__ gamma, const float* __restrict__ beta,
                              float* __restrict__ scale, float* __restrict__ shift) {
    __shared__ float ss[256], sq[256];
    const int c = blockIdx.x;
    const int t = threadIdx.x;
    float s = 0.0f, q = 0.0f;
    for (int i = t; i < PB; i += 256) {
        s += psum[(size_t)i * C + c];
        q += psq [(size_t)i * C + c];
    }
    ss[t] = s; sq[t] = q;
    __syncthreads();
#pragma unroll
    for (int off = 128; off > 0; off >>= 1) {
        if (t < off) { ss[t] += ss[t + off]; sq[t] += sq[t + off]; }
        __syncthreads();
    }
    if (t == 0) {
        const float invn = 1.0f / (float)M_;
        float mean = ss[0] * invn;
        float var  = sq[0] * invn - mean * mean;
        float sc = gamma[c] * rsqrtf(var + BN_EPS);
        scale[c] = sc;
        shift[c] = beta[c] - mean * sc;
    }
}

// ---------------- final BN2 + ReLU ----------------
__global__ void apply_kernel(const float* __restrict__ H,
                             const float* __restrict__ scale, const float* __restrict__ shift,
                             float* __restrict__ out) {
    size_t i = (size_t)blockIdx.x * blockDim.x + threadIdx.x;
    float4 v = ((const float4*)H)[i];
    int c = (int)((i * 4) & (H2_ - 1));
    float4 o;
    o.x = fmaxf(fmaf(v.x, scale[c + 0], shift[c + 0]), 0.0f);
    o.y = fmaxf(fmaf(v.y, scale[c + 1], shift[c + 1]), 0.0f);
    o.z = fmaxf(fmaf(v.z, scale[c + 2], shift[c + 2]), 0.0f);
    o.w = fmaxf(fmaf(v.w, scale[c + 3], shift[c + 3]), 0.0f);
    ((float4*)out)[i] = o;
}

// ---------------- host launcher ----------------
extern "C" void kernel_launch(void* const* d_in, const int* in_sizes, int n_in,
                              void* d_out, int out_size) {
    const float* xyz1    = (const float*)d_in[0];
    const float* xyz2    = (const float*)d_in[1];
    const float* points1 = (const float*)d_in[2];
    const float* points2 = (const float*)d_in[3];
    const float* W1      = (const float*)d_in[4];   // [256 out][384 in] = n-major
    // d_in[5] = b1 : cancels under BatchNorm -> unused
    const float* gamma1  = (const float*)d_in[6];
    const float* beta1   = (const float*)d_in[7];
    const float* W2      = (const float*)d_in[8];   // [128 out][256 in] = n-major
    // d_in[9] = b2 : cancels under BatchNorm -> unused
    const float* gamma2  = (const float*)d_in[10];
    const float* beta2   = (const float*)d_in[11];
    float* out = (float*)d_out;

    float *px, *ph1, *ph2, *pwc1, *pwc2, *pps, *ppq, *psc1, *psh1, *psc2, *psh2;
    cudaGetSymbolAddress((void**)&px,   g_x);
    cudaGetSymbolAddress((void**)&ph1,  g_h1);
    cudaGetSymbolAddress((void**)&ph2,  g_h2);
    cudaGetSymbolAddress((void**)&pwc1, g_wc1);
    cudaGetSymbolAddress((void**)&pwc2, g_wc2);
    cudaGetSymbolAddress((void**)&pps,  g_psum);
    cudaGetSymbolAddress((void**)&ppq,  g_psq);
    cudaGetSymbolAddress((void**)&psc1, g_scale1);
    cudaGetSymbolAddress((void**)&psh1, g_shift1);
    cudaGetSymbolAddress((void**)&psc2, g_scale2);
    cudaGetSymbolAddress((void**)&psh2, g_shift2);

    // opt-in to >48KB dynamic smem for both GEMM instantiations (attribute set,
    // not an allocation; idempotent across calls)
    cudaFuncSetAttribute((const void*)gemm_tc<INCH_, H1_, false>,
                         cudaFuncAttributeMaxDynamicSharedMemorySize, GEMM_SMEM_BYTES);
    cudaFuncSetAttribute((const void*)gemm_tc<H1_, H2_, true>,
                         cudaFuncAttributeMaxDynamicSharedMemorySize, GEMM_SMEM_BYTES);

    // pre-convert weights to tf32 (identical rounding to former in-loop cvt)
    cvt_weights_kernel<<<(H1_ * INCH_ + 255) / 256, 256>>>(W1, pwc1, H1_ * INCH_);
    cvt_weights_kernel<<<(H2_ * H1_  + 255) / 256, 256>>>(W2, pwc2, H2_ * H1_);

    // 3-NN + interpolate + concat -> g_x [M,384] (tf32-rounded)
    {
        dim3 grid(N1_ / QPB, B_);
        knn_interp_kernel<<<grid, KNN_T>>>(xyz1, xyz2, points1, points2, px);
    }

    // GEMM1 (tf32 TC, 3-stage cp.async) + fused BN1 partial stats
    {
        dim3 grid(MT_, H1_ / 128);
        gemm_tc<INCH_, H1_, false><<<grid, 256, GEMM_SMEM_BYTES>>>(
            px, pwc1, nullptr, nullptr, ph1, pps, ppq);
    }
    reduce_kernel<H1_, MT_><<<H1_, 256>>>(pps, ppq, gamma1, beta1, psc1, psh1);

    // GEMM2 (tf32 TC, 3-stage cp.async) with fragment-level BN1+ReLU on A
    {
        dim3 grid(MT_, H2_ / 128);
        gemm_tc<H1_, H2_, true><<<grid, 256, GEMM_SMEM_BYTES>>>(
            ph1, pwc2, psc1, psh1, ph2, pps, ppq);
    }
    reduce_kernel<H2_, MT_><<<H2_, 256>>>(pps, ppq, gamma2, beta2, psc2, psh2);

    // final BN2 + ReLU -> d_out [M,128]
    {
        size_t n4 = (size_t)M_ * H2_ / 4;
        apply_kernel<<<(unsigned)(n4 / 256), 256>>>(ph2, psc2, psh2, out);
    }
}

// round 15
// speedup vs baseline: 1.0614x; 1.0614x over previous
#include <cuda_runtime.h>
#include <cstdint>

#define B_    8
#define N1_   16384
#define N2_   2048
#define C1_   128
#define C2_   256
#define INCH_ 384
#define H1_   256
#define H2_   128
#define M_    (B_ * N1_)            // 131072 rows
#define MT_   (M_ / 128)            // 1024 M-tiles (partial-stat blocks)
#define BN_EPS 1e-5f

// ---------------- scratch (device globals; no cudaMalloc allowed) ----------------
__device__ float g_x  [(size_t)M_ * INCH_];   // concat(points1, interp)  [M,384]
__device__ float g_h1 [(size_t)M_ * H1_];     // GEMM1 out (pre-BN)       [M,256]
__device__ float g_h2 [(size_t)M_ * H2_];     // GEMM2 out (pre-BN)       [M,128]
__device__ float g_psum[(size_t)MT_ * H1_];
__device__ float g_psq [(size_t)MT_ * H1_];
__device__ float g_scale1[H1_], g_shift1[H1_];
__device__ float g_scale2[H2_], g_shift2[H2_];

// ---------------- 3-NN + interpolation + concat ----------------
// Branchless exact top-3: the divergent insert chain is replaced by
// 3 compares + 10 selects (identical strict-< semantics, zero divergence).
#define QPT 4
#define KNN_T 128
#define QPB (QPT * KNN_T)   // 512 queries per block

__global__ __launch_bounds__(KNN_T)
void knn_interp_kernel(const float* __restrict__ xyz1, const float* __restrict__ xyz2,
                       const float* __restrict__ points1, const float* __restrict__ points2,
                       float* __restrict__ x_out) {
    __shared__ float sx[N2_], sy[N2_], sz[N2_];
    __shared__ int   s_idx[QPB][3];
    __shared__ float s_w  [QPB][3];

    const int b   = blockIdx.y;
    const int q0  = blockIdx.x * QPB;
    const int tid = threadIdx.x;

    const float* x2 = xyz2 + (size_t)b * N2_ * 3;
    for (int j = tid; j < N2_; j += KNN_T) {
        float3 v = ((const float3*)x2)[j];
        sx[j] = v.x; sy[j] = v.y; sz[j] = v.z;
    }
    __syncthreads();

    float px[QPT], py[QPT], pz[QPT];
    float d0[QPT], d1[QPT], d2[QPT];
    int   i0[QPT], i1[QPT], i2[QPT];
#pragma unroll
    for (int i = 0; i < QPT; i++) {
        const int q = q0 + i * KNN_T + tid;
        float3 p = ((const float3*)(xyz1 + (size_t)b * N1_ * 3))[q];
        px[i] = p.x; py[i] = p.y; pz[i] = p.z;
        d0[i] = 1e30f; d1[i] = 1e30f; d2[i] = 1e30f;
        i0[i] = 0; i1[i] = 0; i2[i] = 0;
    }

#pragma unroll 4
    for (int j = 0; j < N2_; j++) {
        const float cx = sx[j], cy = sy[j], cz = sz[j];
#pragma unroll
        for (int i = 0; i < QPT; i++) {
            float dx = px[i] - cx;
            float dy = py[i] - cy;
            float dz = pz[i] - cz;
            float d  = fmaf(dx, dx, fmaf(dy, dy, dz * dz));
            // branchless exact insertion (reads of old values precede writes)
            const bool lt0 = d < d0[i];
            const bool lt1 = d < d1[i];
            const bool lt2 = d < d2[i];
            d2[i] = lt1 ? d1[i] : (lt2 ? d : d2[i]);
            i2[i] = lt1 ? i1[i] : (lt2 ? j : i2[i]);
            d1[i] = lt0 ? d0[i] : (lt1 ? d : d1[i]);
            i1[i] = lt0 ? i0[i] : (lt1 ? j : i1[i]);
            d0[i] = lt0 ? d : d0[i];
            i0[i] = lt0 ? j : i0[i];
        }
    }

#pragma unroll
    for (int i = 0; i < QPT; i++) {
        float a0 = 1.0f / fmaxf(d0[i], 1e-10f);
        float a1 = 1.0f / fmaxf(d1[i], 1e-10f);
        float a2 = 1.0f / fmaxf(d2[i], 1e-10f);
        float inv = 1.0f / fmaxf(a0 + a1 + a2, 1e-8f);
        const int lq = i * KNN_T + tid;
        s_idx[lq][0] = i0[i]; s_idx[lq][1] = i1[i]; s_idx[lq][2] = i2[i];
        s_w[lq][0] = a0 * inv; s_w[lq][1] = a1 * inv; s_w[lq][2] = a2 * inv;
    }
    __syncthreads();

    const int warp = tid >> 5, lane = tid & 31;
    const float* p2  = points2 + (size_t)b * N2_ * C2_;
    const float* p1b = points1 + ((size_t)b * N1_ + q0) * C1_;
    float* xb = x_out + ((size_t)b * N1_ + q0) * INCH_;

    for (int lq = warp; lq < QPB; lq += 4) {
        const int   j0 = s_idx[lq][0], j1 = s_idx[lq][1], j2 = s_idx[lq][2];
        const float a0 = s_w[lq][0],   a1 = s_w[lq][1],   a2 = s_w[lq][2];
        const float* r0 = p2 + (size_t)j0 * C2_;
        const float* r1 = p2 + (size_t)j1 * C2_;
        const float* r2 = p2 + (size_t)j2 * C2_;
        float* xrow = xb + (size_t)lq * INCH_;
#pragma unroll
        for (int c = lane; c < C2_; c += 32)
            xrow[C1_ + c] = fmaf(a0, r0[c], fmaf(a1, r1[c], a2 * r2[c]));
        const float* pr = p1b + (size_t)lq * C1_;
#pragma unroll
        for (int c = lane; c < C1_; c += 32)
            xrow[c] = pr[c];
    }
}

// ---------------- tf32 TC GEMM: cp.async 2-stage pipeline + fused BN stats ----------
// (R10 configuration — best measured. In-loop tf32 cvts; one sync per tile.)
// C[M,N] = op(A)[M,K] @ W[N,K]^T. Block 128x128, 8 warps (4M x 2N), BK=16.
// Epilogue: deterministic per-column sum/sum^2 partials -> psum/psq.

__device__ __forceinline__ uint32_t f2tf32(float x) {
    uint32_t u;
    asm("cvt.rna.tf32.f32 %0, %1;" : "=r"(u) : "f"(x));
    return u;
}

#define LDSM4(R, ADDR)                                                          \
    asm volatile("ldmatrix.sync.aligned.m8n8.x4.shared.b16 {%0,%1,%2,%3}, [%4];"\
                 : "=r"(R[0]), "=r"(R[1]), "=r"(R[2]), "=r"(R[3]) : "r"(ADDR))

#define MMA_TF32(D, A, B0, B1)                                                  \
    asm volatile("mma.sync.aligned.m16n8k8.row.col.f32.tf32.tf32.f32 "          \
                 "{%0,%1,%2,%3},{%4,%5,%6,%7},{%8,%9},{%0,%1,%2,%3};"           \
                 : "+f"(D[0]), "+f"(D[1]), "+f"(D[2]), "+f"(D[3])               \
                 : "r"(A[0]), "r"(A[1]), "r"(A[2]), "r"(A[3]), "r"(B0), "r"(B1))

#define CP16(DST, SRC)                                                          \
    asm volatile("cp.async.cg.shared.global [%0], [%1], 16;" :: "r"(DST), "l"(SRC))
#define CP_COMMIT() asm volatile("cp.async.commit_group;")
#define CP_WAIT0()  asm volatile("cp.async.wait_group 0;")

union GemmSmem {
    struct { float As[2][128][20]; float Bs[2][128][20]; } t;   // 40960 B
    struct { float s[128][33]; float q[128][33]; } r;           // 33792 B
};

template <int K, int N, bool BN>
__global__ __launch_bounds__(256, 2)
void gemm_tc(const float* __restrict__ A, const float* __restrict__ W,
             const float* __restrict__ scale, const float* __restrict__ shift,
             float* __restrict__ C,
             float* __restrict__ psum, float* __restrict__ psq) {
    __shared__ GemmSmem sm;

    const int tid  = threadIdx.x;
    const int lane = tid & 31;
    const int warp = tid >> 5;
    const int wm   = warp & 3;
    const int wn   = warp >> 2;
    const int m0   = blockIdx.x * 128;
    const int n0   = blockIdx.y * 128;
    const int l3   = lane & 3;

    const int sr = tid & 127;
    const int sc = (tid >> 7) * 8;
    const float* Ap = A + (size_t)(m0 + sr) * K + sc;
    const float* Wp = W + (size_t)(n0 + sr) * K + sc;
    uint32_t sA[2], sB[2];
#pragma unroll
    for (int bu = 0; bu < 2; bu++) {
        sA[bu] = (uint32_t)__cvta_generic_to_shared(&sm.t.As[bu][sr][sc]);
        sB[bu] = (uint32_t)__cvta_generic_to_shared(&sm.t.Bs[bu][sr][sc]);
    }

    const int r8  = lane & 7;
    const int sel = lane >> 3;
    uint32_t a_addr[2][2][2], b_addr[2][4][2];    // [buf][...][chunk]
#pragma unroll
    for (int bu = 0; bu < 2; bu++) {
        uint32_t ab = (uint32_t)__cvta_generic_to_shared(&sm.t.As[bu][0][0]);
        uint32_t bb = (uint32_t)__cvta_generic_to_shared(&sm.t.Bs[bu][0][0]);
#pragma unroll
        for (int mt = 0; mt < 2; mt++)
#pragma unroll
            for (int c = 0; c < 2; c++)
                a_addr[bu][mt][c] = ab +
                    (((wm * 32 + mt * 16) + r8 + (sel & 1) * 8) * 20 + c * 8 + (sel & 2) * 2) * 4;
#pragma unroll
        for (int p = 0; p < 4; p++)
#pragma unroll
            for (int c = 0; c < 2; c++)
                b_addr[bu][p][c] = bb +
                    (((wn * 64 + p * 16) + r8 + (sel >> 1) * 8) * 20 + c * 8 + (sel & 1) * 4) * 4;
    }

    float acc[2][8][4];
#pragma unroll
    for (int mt = 0; mt < 2; mt++)
#pragma unroll
        for (int nt = 0; nt < 8; nt++)
#pragma unroll
            for (int i = 0; i < 4; i++) acc[mt][nt][i] = 0.0f;

    // prologue: issue tile 0
    CP16(sA[0],      Ap);
    CP16(sA[0] + 16, Ap + 4);
    CP16(sB[0],      Wp);
    CP16(sB[0] + 16, Wp + 4);
    CP_COMMIT();

    const int KT = K / 16;
#pragma unroll 1
    for (int kt = 0; kt < KT; kt++) {
        const int buf = kt & 1;
        CP_WAIT0();
        // Single barrier per tile: proves (a) tile kt visible to all,
        // (b) every warp finished computing tile kt-1, so buf^1 is free
        // for the cp.async issued just below.
        __syncthreads();
        if (kt + 1 < KT) {
            const int k0n = (kt + 1) * 16;
            const int nb  = buf ^ 1;
            CP16(sA[nb],      Ap + k0n);
            CP16(sA[nb] + 16, Ap + k0n + 4);
            CP16(sB[nb],      Wp + k0n);
            CP16(sB[nb] + 16, Wp + k0n + 4);
            CP_COMMIT();
        }

        float bns[2][2], bnh[2][2];      // [chunk][khalf]
        if (BN) {
            const int kb = kt * 16 + l3;
#pragma unroll
            for (int c = 0; c < 2; c++)
#pragma unroll
                for (int h = 0; h < 2; h++) {
                    bns[c][h] = scale[kb + c * 8 + h * 4];
                    bnh[c][h] = shift[kb + c * 8 + h * 4];
                }
        }

#pragma unroll
        for (int c = 0; c < 2; c++) {
            uint32_t af[2][4];
            LDSM4(af[0], a_addr[buf][0][c]);
            LDSM4(af[1], a_addr[buf][1][c]);
            uint32_t bf[4][4];
#pragma unroll
            for (int p = 0; p < 4; p++) LDSM4(bf[p], b_addr[buf][p][c]);

#pragma unroll
            for (int mt = 0; mt < 2; mt++)
#pragma unroll
                for (int r = 0; r < 4; r++) {
                    float v = __uint_as_float(af[mt][r]);
                    if (BN) v = fmaxf(fmaf(v, bns[c][(r >> 1) & 1], bnh[c][(r >> 1) & 1]), 0.0f);
                    af[mt][r] = f2tf32(v);
                }
#pragma unroll
            for (int p = 0; p < 4; p++)
#pragma unroll
                for (int r = 0; r < 4; r++)
                    bf[p][r] = f2tf32(__uint_as_float(bf[p][r]));

#pragma unroll
            for (int mt = 0; mt < 2; mt++)
#pragma unroll
                for (int nt = 0; nt < 8; nt++) {
                    const int p = nt >> 1, wh = nt & 1;
                    MMA_TF32(acc[mt][nt], af[mt], bf[p][wh * 2], bf[p][wh * 2 + 1]);
                }
        }
    }

    // ---- write C tile ----
    const int rr = lane >> 2;
    const int cc = l3 * 2;
#pragma unroll
    for (int mt = 0; mt < 2; mt++)
#pragma unroll
        for (int nt = 0; nt < 8; nt++) {
            const int row = m0 + wm * 32 + mt * 16 + rr;
            const int col = n0 + wn * 64 + nt * 8 + cc;
            float2 v0 = { acc[mt][nt][0], acc[mt][nt][1] };
            float2 v1 = { acc[mt][nt][2], acc[mt][nt][3] };
            *(float2*)&C[(size_t)row * N + col]       = v0;
            *(float2*)&C[(size_t)(row + 8) * N + col] = v1;
        }

    // ---- fused per-block BN stats (deterministic fixed-order reduction) ----
    __syncthreads();
    const int contrib = wm * 8 + rr;
#pragma unroll
    for (int nt = 0; nt < 8; nt++)
#pragma unroll
        for (int d = 0; d < 2; d++) {
            const int colL = wn * 64 + nt * 8 + cc + d;
            float s = 0.0f, q = 0.0f;
#pragma unroll
            for (int mt = 0; mt < 2; mt++) {
                float v0 = acc[mt][nt][d];
                float v1 = acc[mt][nt][d + 2];
                s += v0 + v1;
                q += v0 * v0 + v1 * v1;
            }
            sm.r.s[colL][contrib] = s;
            sm.r.q[colL][contrib] = q;
        }
    __syncthreads();
    if (tid < 128) {
        float s = 0.0f, q = 0.0f;
#pragma unroll 8
        for (int i = 0; i < 32; i++) { s += sm.r.s[tid][i]; q += sm.r.q[tid][i]; }
        psum[(size_t)blockIdx.x * N + n0 + tid] = s;
        psq [(size_t)blockIdx.x * N + n0 + tid] = q;
    }
}

// ---------------- parallel BN reduce: one block per channel ----------------
template <int C, int PB>
__global__ void reduce_kernel(const float* __restrict__ psum, const float* __restrict__ psq,
                              const float* __restrict__ gamma, const float* __restrict__ beta,
                              float* __restrict__ scale, float* __restrict__ shift) {
    __shared__ float ss[256], sq[256];
    const int c = blockIdx.x;
    const int t = threadIdx.x;
    float s = 0.0f, q = 0.0f;
    for (int i = t; i < PB; i += 256) {
        s += psum[(size_t)i * C + c];
        q += psq [(size_t)i * C + c];
    }
    ss[t] = s; sq[t] = q;
    __syncthreads();
#pragma unroll
    for (int off = 128; off > 0; off >>= 1) {
        if (t < off) { ss[t] += ss[t + off]; sq[t] += sq[t + off]; }
        __syncthreads();
    }
    if (t == 0) {
        const float invn = 1.0f / (float)M_;
        float mean = ss[0] * invn;
        float var  = sq[0] * invn - mean * mean;
        float sc = gamma[c] * rsqrtf(var + BN_EPS);
        scale[c] = sc;
        shift[c] = beta[c] - mean * sc;
    }
}

// ---------------- final BN2 + ReLU ----------------
__global__ void apply_kernel(const float* __restrict__ H,
                             const float* __restrict__ scale, const float* __restrict__ shift,
                             float* __restrict__ out) {
    size_t i = (size_t)blockIdx.x * blockDim.x + threadIdx.x;
    float4 v = ((const float4*)H)[i];
    int c = (int)((i * 4) & (H2_ - 1));
    float4 o;
    o.x = fmaxf(fmaf(v.x, scale[c + 0], shift[c + 0]), 0.0f);
    o.y = fmaxf(fmaf(v.y, scale[c + 1], shift[c + 1]), 0.0f);
    o.z = fmaxf(fmaf(v.z, scale[c + 2], shift[c + 2]), 0.0f);
    o.w = fmaxf(fmaf(v.w, scale[c + 3], shift[c + 3]), 0.0f);
    ((float4*)out)[i] = o;
}

// ---------------- host launcher ----------------
extern "C" void kernel_launch(void* const* d_in, const int* in_sizes, int n_in,
                              void* d_out, int out_size) {
    const float* xyz1    = (const float*)d_in[0];
    const float* xyz2    = (const float*)d_in[1];
    const float* points1 = (const float*)d_in[2];
    const float* points2 = (const float*)d_in[3];
    const float* W1      = (const float*)d_in[4];   // [256 out][384 in] = n-major
    // d_in[5] = b1 : cancels under BatchNorm -> unused
    const float* gamma1  = (const float*)d_in[6];
    const float* beta1   = (const float*)d_in[7];
    const float* W2      = (const float*)d_in[8];   // [128 out][256 in] = n-major
    // d_in[9] = b2 : cancels under BatchNorm -> unused
    const float* gamma2  = (const float*)d_in[10];
    const float* beta2   = (const float*)d_in[11];
    float* out = (float*)d_out;

    float *px, *ph1, *ph2, *pps, *ppq, *psc1, *psh1, *psc2, *psh2;
    cudaGetSymbolAddress((void**)&px,   g_x);
    cudaGetSymbolAddress((void**)&ph1,  g_h1);
    cudaGetSymbolAddress((void**)&ph2,  g_h2);
    cudaGetSymbolAddress((void**)&pps,  g_psum);
    cudaGetSymbolAddress((void**)&ppq,  g_psq);
    cudaGetSymbolAddress((void**)&psc1, g_scale1);
    cudaGetSymbolAddress((void**)&psh1, g_shift1);
    cudaGetSymbolAddress((void**)&psc2, g_scale2);
    cudaGetSymbolAddress((void**)&psh2, g_shift2);

    // 3-NN + interpolate + concat -> g_x [M,384]
    {
        dim3 grid(N1_ / QPB, B_);
        knn_interp_kernel<<<grid, KNN_T>>>(xyz1, xyz2, points1, points2, px);
    }

    // GEMM1 (tf32 TC, cp.async 2-stage) + fused BN1 partial stats
    {
        dim3 grid(MT_, H1_ / 128);
        gemm_tc<INCH_, H1_, false><<<grid, 256>>>(px, W1, nullptr, nullptr, ph1, pps, ppq);
    }
    reduce_kernel<H1_, MT_><<<H1_, 256>>>(pps, ppq, gamma1, beta1, psc1, psh1);

    // GEMM2 (tf32 TC, cp.async 2-stage) with fragment-level BN1+ReLU on A
    {
        dim3 grid(MT_, H2_ / 128);
        gemm_tc<H1_, H2_, true><<<grid, 256>>>(ph1, W2, psc1, psh1, ph2, pps, ppq);
    }
    reduce_kernel<H2_, MT_><<<H2_, 256>>>(pps, ppq, gamma2, beta2, psc2, psh2);

    // final BN2 + ReLU -> d_out [M,128]
    {
        size_t n4 = (size_t)M_ * H2_ / 4;
        apply_kernel<<<(unsigned)(n4 / 256), 256>>>(ph2, psc2, psh2, out);
    }
}